// round 2
// baseline (speedup 1.0000x reference)
#include <cuda_runtime.h>
#include <math_constants.h>

#define BATCH   256
#define DIM     512
#define DIM2    1024
#define NGATE   2048
#define NNODES  262144
#define STEPS   6

// ---- persistent scratch (no allocs allowed) ----
__device__ float g_h[BATCH * DIM];
__device__ float g_c[BATCH * DIM];
__device__ float g_qstar[BATCH * DIM2];
__device__ float g_gates[BATCH * NGATE];
__device__ int   g_seg[BATCH + 1];
__device__ int   g_is32;   // 1 if batch is int32, 0 if int64

// ---------------------------------------------------------------------------
// zero-init state (h, c, q_star)
// ---------------------------------------------------------------------------
__global__ void k_init() {
    int i = blockIdx.x * blockDim.x + threadIdx.x;
    if (i < BATCH * DIM)  { g_h[i] = 0.f; g_c[i] = 0.f; }
    if (i < BATCH * DIM2) { g_qstar[i] = 0.f; }
}

// ---------------------------------------------------------------------------
// detect batch dtype: view buffer as int32 words. For int64 (little-endian),
// odd word indices are high words == 0 (values < 256). For int32, odd indices
// are batch values, mostly nonzero. Scan only first NNODES words (safe for
// both layouts).
// ---------------------------------------------------------------------------
__global__ void k_detect(const int* __restrict__ bw) {
    __shared__ int flag;
    if (threadIdx.x == 0) flag = 0;
    __syncthreads();
    int found = 0;
    for (int i = 1 + 2 * threadIdx.x; i < NNODES; i += 2 * blockDim.x)
        if (bw[i] != 0) { found = 1; break; }
    if (found) atomicOr(&flag, 1);
    __syncthreads();
    if (threadIdx.x == 0) g_is32 = flag;
}

// ---------------------------------------------------------------------------
// segment offsets via binary search on sorted batch (dtype-agnostic)
// ---------------------------------------------------------------------------
__global__ void k_seg(const int* __restrict__ bw) {
    int b = threadIdx.x;
    if (b > BATCH) return;
    const int is32 = g_is32;
    int lo = 0, hi = NNODES;
    while (lo < hi) {
        int mid = (lo + hi) >> 1;
        int v = is32 ? bw[mid] : bw[2 * mid];   // low word of int64
        if (v < b) lo = mid + 1; else hi = mid;
    }
    g_seg[b] = lo;
}

// ---------------------------------------------------------------------------
// gates = q_star @ w_ih^T + h @ w_hh^T + b_ih + b_hh
// Tiled fp32 GEMM: 64x64 block tile, 256 threads, 4x4 per thread.
// ---------------------------------------------------------------------------
__global__ __launch_bounds__(256) void k_gemm(const float* __restrict__ w_ih,
                                              const float* __restrict__ w_hh,
                                              const float* __restrict__ b_ih,
                                              const float* __restrict__ b_hh) {
    __shared__ float As[16][68];
    __shared__ float Bs[16][68];

    const int tid = threadIdx.x;
    const int tx = tid & 15;        // n micro index
    const int ty = tid >> 4;        // m micro index
    const int m0 = blockIdx.y * 64;
    const int n0 = blockIdx.x * 64;

    float acc[4][4];
#pragma unroll
    for (int i = 0; i < 4; ++i)
#pragma unroll
        for (int j = 0; j < 4; ++j) acc[i][j] = 0.f;

    const int lr = tid >> 2;          // 0..63 : row within tile
    const int lk = (tid & 3) << 2;    // 0,4,8,12 : k group

#pragma unroll
    for (int op = 0; op < 2; ++op) {
        const float* A = op ? g_h : g_qstar;
        const float* W = op ? w_hh : w_ih;
        const int    K = op ? DIM : DIM2;
        for (int k0 = 0; k0 < K; k0 += 16) {
            float4 av = *(const float4*)&A[(size_t)(m0 + lr) * K + k0 + lk];
            float4 wv = *(const float4*)&W[(size_t)(n0 + lr) * K + k0 + lk];
            As[lk + 0][lr] = av.x; As[lk + 1][lr] = av.y;
            As[lk + 2][lr] = av.z; As[lk + 3][lr] = av.w;
            Bs[lk + 0][lr] = wv.x; Bs[lk + 1][lr] = wv.y;
            Bs[lk + 2][lr] = wv.z; Bs[lk + 3][lr] = wv.w;
            __syncthreads();
#pragma unroll
            for (int kk = 0; kk < 16; ++kk) {
                float4 a = *(const float4*)&As[kk][ty << 2];
                float4 b = *(const float4*)&Bs[kk][tx << 2];
                float aa[4] = {a.x, a.y, a.z, a.w};
                float bb[4] = {b.x, b.y, b.z, b.w};
#pragma unroll
                for (int i = 0; i < 4; ++i)
#pragma unroll
                    for (int j = 0; j < 4; ++j) acc[i][j] += aa[i] * bb[j];
            }
            __syncthreads();
        }
    }

#pragma unroll
    for (int j = 0; j < 4; ++j) {
        int n = n0 + (tx << 2) + j;
        float bias = b_ih[n] + b_hh[n];
#pragma unroll
        for (int i = 0; i < 4; ++i) {
            int m = m0 + (ty << 2) + i;
            g_gates[(size_t)m * NGATE + n] = acc[i][j] + bias;
        }
    }
}

// ---------------------------------------------------------------------------
// LSTM pointwise: gates -> (h, c), also q_star[:, :512] = h
// ---------------------------------------------------------------------------
__device__ __forceinline__ float sigm(float v) { return 1.f / (1.f + expf(-v)); }

__global__ void k_lstm() {
    int idx = blockIdx.x * blockDim.x + threadIdx.x;
    if (idx >= BATCH * DIM) return;
    int m = idx >> 9;
    int j = idx & 511;
    const float* gr = &g_gates[(size_t)m * NGATE];
    float i_ = sigm(gr[j]);
    float f_ = sigm(gr[512 + j]);
    float g_ = tanhf(gr[1024 + j]);
    float o_ = sigm(gr[1536 + j]);
    float c = f_ * g_c[idx] + i_ * g_;
    float h = o_ * tanhf(c);
    g_c[idx] = c;
    g_h[idx] = h;
    g_qstar[(size_t)m * DIM2 + j] = h;
}

// ---------------------------------------------------------------------------
// Segment attention: one CTA per graph, online softmax, x read exactly once.
// 256 threads = 8 warps. Each warp strides over its segment's nodes; lane l
// owns channels {c2*128 + 4l + c} for c2,c in [0,4).
// ---------------------------------------------------------------------------
__global__ __launch_bounds__(256) void k_attn(const float* __restrict__ x) {
    const int b = blockIdx.x;
    const int s = g_seg[b];
    const int e = g_seg[b + 1];

    __shared__ float q_s[DIM];
    __shared__ float r_s[DIM];
    __shared__ float m_s[8];
    __shared__ float d_s[8];

    const int tid = threadIdx.x;
    const int lane = tid & 31;
    const int w = tid >> 5;

    q_s[tid]       = g_h[(size_t)b * DIM + tid];
    q_s[tid + 256] = g_h[(size_t)b * DIM + tid + 256];
    r_s[tid] = 0.f; r_s[tid + 256] = 0.f;
    __syncthreads();

    if (s == e) {  // empty segment: r = 0
        g_qstar[(size_t)b * DIM2 + DIM + tid] = 0.f;
        g_qstar[(size_t)b * DIM2 + DIM + tid + 256] = 0.f;
        return;
    }

    float qr[16];
#pragma unroll
    for (int c2 = 0; c2 < 4; ++c2)
#pragma unroll
        for (int c = 0; c < 4; ++c)
            qr[c2 * 4 + c] = q_s[c2 * 128 + (lane << 2) + c];

    float m = -CUDART_INF_F;
    float d = 0.f;
    float acc[16];
#pragma unroll
    for (int j = 0; j < 16; ++j) acc[j] = 0.f;

    for (int n = s + w; n < e; n += 8) {
        const float4* xp = (const float4*)(x + (size_t)n * DIM);
        float4 v0 = xp[lane];
        float4 v1 = xp[lane + 32];
        float4 v2 = xp[lane + 64];
        float4 v3 = xp[lane + 96];
        float xv[16] = {v0.x, v0.y, v0.z, v0.w,
                        v1.x, v1.y, v1.z, v1.w,
                        v2.x, v2.y, v2.z, v2.w,
                        v3.x, v3.y, v3.z, v3.w};
        float dot = 0.f;
#pragma unroll
        for (int j = 0; j < 16; ++j) dot += xv[j] * qr[j];
#pragma unroll
        for (int off = 16; off; off >>= 1)
            dot += __shfl_xor_sync(0xffffffffu, dot, off);

        float mn = fmaxf(m, dot);
        float sc = expf(m - mn);      // -inf first time -> 0
        float wt = expf(dot - mn);
        d = d * sc + wt;
#pragma unroll
        for (int j = 0; j < 16; ++j) acc[j] = acc[j] * sc + wt * xv[j];
        m = mn;
    }

    if (lane == 0) m_s[w] = m;
    __syncthreads();
    float M = m_s[0];
#pragma unroll
    for (int k = 1; k < 8; ++k) M = fmaxf(M, m_s[k]);
    float f = expf(m - M);            // empty-warp (m=-inf) -> 0
    if (lane == 0) d_s[w] = d * f;
#pragma unroll
    for (int c2 = 0; c2 < 4; ++c2)
#pragma unroll
        for (int c = 0; c < 4; ++c)
            atomicAdd(&r_s[c2 * 128 + (lane << 2) + c], acc[c2 * 4 + c] * f);
    __syncthreads();

    float D = 0.f;
#pragma unroll
    for (int k = 0; k < 8; ++k) D += d_s[k];
    float inv = 1.f / (D + 1e-16f);

    g_qstar[(size_t)b * DIM2 + DIM + tid]       = r_s[tid] * inv;
    g_qstar[(size_t)b * DIM2 + DIM + tid + 256] = r_s[tid + 256] * inv;
}

// ---------------------------------------------------------------------------
// final copy q_star -> d_out
// ---------------------------------------------------------------------------
__global__ void k_copy(float* __restrict__ out) {
    int i = blockIdx.x * blockDim.x + threadIdx.x;
    if (i < BATCH * DIM2) out[i] = g_qstar[i];
}

// ---------------------------------------------------------------------------
extern "C" void kernel_launch(void* const* d_in, const int* in_sizes, int n_in,
                              void* d_out, int out_size) {
    const float* x     = (const float*)d_in[0];
    const int*   batch = (const int*)d_in[1];   // dtype detected at runtime
    const float* w_ih  = (const float*)d_in[2];
    const float* w_hh  = (const float*)d_in[3];
    const float* b_ih  = (const float*)d_in[4];
    const float* b_hh  = (const float*)d_in[5];

    k_init<<<(BATCH * DIM2 + 255) / 256, 256>>>();
    k_detect<<<1, 256>>>(batch);
    k_seg<<<1, BATCH + 1>>>(batch);

    dim3 ggrid(NGATE / 64, BATCH / 64);
    for (int step = 0; step < STEPS; ++step) {
        k_gemm<<<ggrid, 256>>>(w_ih, w_hh, b_ih, b_hh);
        k_lstm<<<(BATCH * DIM + 255) / 256, 256>>>();
        k_attn<<<BATCH, 256>>>(x);
    }
    k_copy<<<(BATCH * DIM2 + 255) / 256, 256>>>((float*)d_out);
}

// round 3
// speedup vs baseline: 1.5013x; 1.5013x over previous
#include <cuda_runtime.h>
#include <math_constants.h>

#define BATCH   256
#define DIM     512
#define DIM2    1024
#define NGATE   2048
#define NNODES  262144
#define STEPS   6
#define NSPLIT  2          // attention segment split

// ---- persistent scratch (no allocs allowed) ----
__device__ float g_h[BATCH * DIM];
__device__ float g_c[BATCH * DIM];
__device__ float g_qstar[BATCH * DIM2];
__device__ float g_gates0[BATCH * NGATE];
__device__ float g_gates1[BATCH * NGATE];
__device__ float g_wsum[NGATE * DIM];     // w_ih[:, :512] + w_hh
__device__ float g_bias[NGATE];           // b_ih + b_hh
__device__ int   g_seg[BATCH + 1];
__device__ int   g_is32;
// attention partials
__device__ float g_pm[BATCH * NSPLIT];
__device__ float g_pd[BATCH * NSPLIT];
__device__ float g_pr[BATCH * NSPLIT * DIM];

// ---------------------------------------------------------------------------
__global__ void k_init() {
    int i = blockIdx.x * blockDim.x + threadIdx.x;
    if (i < BATCH * DIM)  { g_h[i] = 0.f; g_c[i] = 0.f; }
    if (i < BATCH * DIM2) { g_qstar[i] = 0.f; }
}

// precompute w_sum = w_ih[:, :512] + w_hh  and bias = b_ih + b_hh
__global__ void k_prep(const float* __restrict__ w_ih,
                       const float* __restrict__ w_hh,
                       const float* __restrict__ b_ih,
                       const float* __restrict__ b_hh) {
    int i = blockIdx.x * blockDim.x + threadIdx.x;
    if (i < NGATE * DIM) {
        int n = i >> 9;        // row
        int k = i & 511;       // col
        g_wsum[i] = w_ih[(size_t)n * DIM2 + k] + w_hh[i];
    }
    if (i < NGATE) g_bias[i] = b_ih[i] + b_hh[i];
}

// ---------------------------------------------------------------------------
// batch dtype detect (int32 vs int64) + segment offsets
// ---------------------------------------------------------------------------
__global__ void k_detect(const int* __restrict__ bw) {
    __shared__ int flag;
    if (threadIdx.x == 0) flag = 0;
    __syncthreads();
    int found = 0;
    for (int i = 1 + 2 * threadIdx.x; i < NNODES; i += 2 * blockDim.x)
        if (bw[i] != 0) { found = 1; break; }
    if (found) atomicOr(&flag, 1);
    __syncthreads();
    if (threadIdx.x == 0) g_is32 = flag;
}

__global__ void k_seg(const int* __restrict__ bw) {
    int b = threadIdx.x;
    if (b > BATCH) return;
    const int is32 = g_is32;
    int lo = 0, hi = NNODES;
    while (lo < hi) {
        int mid = (lo + hi) >> 1;
        int v = is32 ? bw[mid] : bw[2 * mid];
        if (v < b) lo = mid + 1; else hi = mid;
    }
    g_seg[b] = lo;
}

// ---------------------------------------------------------------------------
// split-K GEMM: z=0 : g_gates0 = h @ g_wsum^T        (K=512)
//               z=1 : g_gates1 = r @ w_ih[:,512:]^T  (K=512)
// 64x64 tile, 256 threads, 4x4 micro, double-buffered smem.
// ---------------------------------------------------------------------------
__global__ __launch_bounds__(256) void k_gemm2(const float* __restrict__ w_ih) {
    __shared__ float As[2][16][68];
    __shared__ float Bs[2][16][68];

    const int s = blockIdx.z;
    const float* A   = s ? (g_qstar + DIM) : g_h;
    const int    lda = s ? DIM2 : DIM;
    const float* W   = s ? (w_ih + DIM) : g_wsum;
    const int    ldw = s ? DIM2 : DIM;
    float* out       = s ? g_gates1 : g_gates0;

    const int tid = threadIdx.x;
    const int tx = tid & 15;
    const int ty = tid >> 4;
    const int m0 = blockIdx.y * 64;
    const int n0 = blockIdx.x * 64;

    const int lr = tid >> 2;
    const int lk = (tid & 3) << 2;

    float acc[4][4];
#pragma unroll
    for (int i = 0; i < 4; ++i)
#pragma unroll
        for (int j = 0; j < 4; ++j) acc[i][j] = 0.f;

    // prologue: load tile 0
    float4 av = *(const float4*)&A[(size_t)(m0 + lr) * lda + lk];
    float4 wv = *(const float4*)&W[(size_t)(n0 + lr) * ldw + lk];
    As[0][lk + 0][lr] = av.x; As[0][lk + 1][lr] = av.y;
    As[0][lk + 2][lr] = av.z; As[0][lk + 3][lr] = av.w;
    Bs[0][lk + 0][lr] = wv.x; Bs[0][lk + 1][lr] = wv.y;
    Bs[0][lk + 2][lr] = wv.z; Bs[0][lk + 3][lr] = wv.w;
    __syncthreads();

    const int NT = DIM / 16;   // 32 k-tiles
    for (int kt = 0; kt < NT; ++kt) {
        int cur = kt & 1;
        if (kt + 1 < NT) {
            int k0 = (kt + 1) * 16;
            av = *(const float4*)&A[(size_t)(m0 + lr) * lda + k0 + lk];
            wv = *(const float4*)&W[(size_t)(n0 + lr) * ldw + k0 + lk];
        }
#pragma unroll
        for (int kk = 0; kk < 16; ++kk) {
            float4 a = *(const float4*)&As[cur][kk][ty << 2];
            float4 b = *(const float4*)&Bs[cur][kk][tx << 2];
            float aa[4] = {a.x, a.y, a.z, a.w};
            float bb[4] = {b.x, b.y, b.z, b.w};
#pragma unroll
            for (int i = 0; i < 4; ++i)
#pragma unroll
                for (int j = 0; j < 4; ++j) acc[i][j] += aa[i] * bb[j];
        }
        if (kt + 1 < NT) {
            int nxt = cur ^ 1;
            As[nxt][lk + 0][lr] = av.x; As[nxt][lk + 1][lr] = av.y;
            As[nxt][lk + 2][lr] = av.z; As[nxt][lk + 3][lr] = av.w;
            Bs[nxt][lk + 0][lr] = wv.x; Bs[nxt][lk + 1][lr] = wv.y;
            Bs[nxt][lk + 2][lr] = wv.z; Bs[nxt][lk + 3][lr] = wv.w;
            __syncthreads();
        }
    }

#pragma unroll
    for (int j = 0; j < 4; ++j) {
        int n = n0 + (tx << 2) + j;
#pragma unroll
        for (int i = 0; i < 4; ++i) {
            int m = m0 + (ty << 2) + i;
            out[(size_t)m * NGATE + n] = acc[i][j];
        }
    }
}

// ---------------------------------------------------------------------------
// LSTM pointwise: gates = g0 + g1 + bias  ->  (h, c), q_star[:, :512] = h
// ---------------------------------------------------------------------------
__device__ __forceinline__ float sigm(float v) { return 1.f / (1.f + expf(-v)); }

__global__ void k_lstm() {
    int idx = blockIdx.x * blockDim.x + threadIdx.x;
    if (idx >= BATCH * DIM) return;
    int m = idx >> 9;
    int j = idx & 511;
    size_t base = (size_t)m * NGATE;
#define GATE(n) (g_gates0[base + (n)] + g_gates1[base + (n)] + g_bias[(n)])
    float i_ = sigm(GATE(j));
    float f_ = sigm(GATE(512 + j));
    float g_ = tanhf(GATE(1024 + j));
    float o_ = sigm(GATE(1536 + j));
#undef GATE
    float c = f_ * g_c[idx] + i_ * g_;
    float h = o_ * tanhf(c);
    g_c[idx] = c;
    g_h[idx] = h;
    g_qstar[(size_t)m * DIM2 + j] = h;
}

// ---------------------------------------------------------------------------
// attention partial: CTA (b, p) handles half p of segment b with online
// softmax. Writes unnormalized partial (m, d, r[512]).
// 256 threads = 8 warps. lane l owns channels c2*128 + 4l + c.
// ---------------------------------------------------------------------------
__global__ __launch_bounds__(256) void k_attn_part(const float* __restrict__ x) {
    const int b = blockIdx.x >> 1;
    const int p = blockIdx.x & 1;
    const int s0 = g_seg[b], e0 = g_seg[b + 1];
    const int mid = s0 + ((e0 - s0) >> 1);
    const int s = p ? mid : s0;
    const int e = p ? e0 : mid;

    const int tid = threadIdx.x;
    const int lane = tid & 31;
    const int w = tid >> 5;

    __shared__ float q_s[DIM];
    __shared__ float part[8][DIM];   // per-warp scaled accumulators
    __shared__ float m_s[8];
    __shared__ float d_s[8];

    float* pr = &g_pr[(size_t)blockIdx.x * DIM];

    if (s >= e) {
        if (tid == 0) { g_pm[blockIdx.x] = -CUDART_INF_F; g_pd[blockIdx.x] = 0.f; }
        pr[tid] = 0.f; pr[tid + 256] = 0.f;
        return;
    }

    q_s[tid]       = g_h[(size_t)b * DIM + tid];
    q_s[tid + 256] = g_h[(size_t)b * DIM + tid + 256];
    __syncthreads();

    float qr[16];
#pragma unroll
    for (int c2 = 0; c2 < 4; ++c2)
#pragma unroll
        for (int c = 0; c < 4; ++c)
            qr[c2 * 4 + c] = q_s[c2 * 128 + (lane << 2) + c];

    float m = -CUDART_INF_F;
    float d = 0.f;
    float acc[16];
#pragma unroll
    for (int j = 0; j < 16; ++j) acc[j] = 0.f;

    int n = s + w;
    float4 cur0, cur1, cur2, cur3;
    if (n < e) {
        const float4* xp = (const float4*)(x + (size_t)n * DIM);
        cur0 = __ldcs(xp + lane);
        cur1 = __ldcs(xp + lane + 32);
        cur2 = __ldcs(xp + lane + 64);
        cur3 = __ldcs(xp + lane + 96);
    }
    for (; n < e; n += 8) {
        float4 n0, n1, n2, n3;
        if (n + 8 < e) {
            const float4* xp = (const float4*)(x + (size_t)(n + 8) * DIM);
            n0 = __ldcs(xp + lane);
            n1 = __ldcs(xp + lane + 32);
            n2 = __ldcs(xp + lane + 64);
            n3 = __ldcs(xp + lane + 96);
        }
        float xv[16] = {cur0.x, cur0.y, cur0.z, cur0.w,
                        cur1.x, cur1.y, cur1.z, cur1.w,
                        cur2.x, cur2.y, cur2.z, cur2.w,
                        cur3.x, cur3.y, cur3.z, cur3.w};
        float dot = 0.f;
#pragma unroll
        for (int j = 0; j < 16; ++j) dot += xv[j] * qr[j];
#pragma unroll
        for (int off = 16; off; off >>= 1)
            dot += __shfl_xor_sync(0xffffffffu, dot, off);

        float mn = fmaxf(m, dot);
        float sc = expf(m - mn);
        float wt = expf(dot - mn);
        d = d * sc + wt;
#pragma unroll
        for (int j = 0; j < 16; ++j) acc[j] = acc[j] * sc + wt * xv[j];
        m = mn;
        cur0 = n0; cur1 = n1; cur2 = n2; cur3 = n3;
    }

    if (lane == 0) m_s[w] = m;
    __syncthreads();
    float M = m_s[0];
#pragma unroll
    for (int k = 1; k < 8; ++k) M = fmaxf(M, m_s[k]);
    float f = (m == -CUDART_INF_F) ? 0.f : expf(m - M);
    if (lane == 0) d_s[w] = d * f;
#pragma unroll
    for (int c2 = 0; c2 < 4; ++c2)
#pragma unroll
        for (int c = 0; c < 4; ++c)
            part[w][c2 * 128 + (lane << 2) + c] = acc[c2 * 4 + c] * f;
    __syncthreads();

    if (tid == 0) {
        float D = 0.f;
#pragma unroll
        for (int k = 0; k < 8; ++k) D += d_s[k];
        g_pm[blockIdx.x] = M;
        g_pd[blockIdx.x] = D;
    }
#pragma unroll
    for (int rep = 0; rep < 2; ++rep) {
        int c = tid + rep * 256;
        float v = 0.f;
#pragma unroll
        for (int k = 0; k < 8; ++k) v += part[k][c];
        pr[c] = v;
    }
}

// combine the two partials per segment -> q_star[:, 512:]
__global__ __launch_bounds__(256) void k_attn_comb() {
    const int b = blockIdx.x;
    const int tid = threadIdx.x;
    float m0 = g_pm[2 * b], m1 = g_pm[2 * b + 1];
    float M = fmaxf(m0, m1);
    float f0 = (m0 == -CUDART_INF_F) ? 0.f : expf(m0 - M);
    float f1 = (m1 == -CUDART_INF_F) ? 0.f : expf(m1 - M);
    if (M == -CUDART_INF_F) { f0 = 0.f; f1 = 0.f; }
    float D = g_pd[2 * b] * f0 + g_pd[2 * b + 1] * f1;
    float inv = 1.f / (D + 1e-16f);
    const float* r0 = &g_pr[(size_t)(2 * b) * DIM];
    const float* r1 = &g_pr[(size_t)(2 * b + 1) * DIM];
#pragma unroll
    for (int rep = 0; rep < 2; ++rep) {
        int c = tid + rep * 256;
        g_qstar[(size_t)b * DIM2 + DIM + c] = (r0[c] * f0 + r1[c] * f1) * inv;
    }
}

// ---------------------------------------------------------------------------
__global__ void k_copy(float* __restrict__ out) {
    int i = blockIdx.x * blockDim.x + threadIdx.x;
    if (i < BATCH * DIM2) out[i] = g_qstar[i];
}

// ---------------------------------------------------------------------------
extern "C" void kernel_launch(void* const* d_in, const int* in_sizes, int n_in,
                              void* d_out, int out_size) {
    const float* x     = (const float*)d_in[0];
    const int*   batch = (const int*)d_in[1];
    const float* w_ih  = (const float*)d_in[2];
    const float* w_hh  = (const float*)d_in[3];
    const float* b_ih  = (const float*)d_in[4];
    const float* b_hh  = (const float*)d_in[5];

    k_init<<<(BATCH * DIM2 + 255) / 256, 256>>>();
    k_prep<<<(NGATE * DIM + 255) / 256, 256>>>(w_ih, w_hh, b_ih, b_hh);
    k_detect<<<1, 256>>>(batch);
    k_seg<<<1, BATCH + 1>>>(batch);

    dim3 ggrid(NGATE / 64, BATCH / 64, 2);
    for (int step = 0; step < STEPS; ++step) {
        k_gemm2<<<ggrid, 256>>>(w_ih);
        k_lstm<<<(BATCH * DIM + 255) / 256, 256>>>();
        k_attn_part<<<BATCH * NSPLIT, 256>>>(x);
        k_attn_comb<<<BATCH, 256>>>();
    }
    k_copy<<<(BATCH * DIM2 + 255) / 256, 256>>>((float*)d_out);
}